// round 1
// baseline (speedup 1.0000x reference)
#include <cuda_runtime.h>
#include <math.h>

#define Bn 8
#define Nn 2048
#define Fn 128
#define MAXNBR 256
#define NEG_INF_IN (-1000000000.0f)

// Scratch (allocation-free rule: __device__ globals)
__device__ float g_h[Bn * Nn * Fn];      // 8 MB
__device__ float g_esrc[Bn * Nn];
__device__ float g_edst[Bn * Nn];
__device__ int   g_nbr[Nn * MAXNBR];     // 2 MB
__device__ int   g_cnt[Nn];

// ---------------------------------------------------------------------------
// Kernel 1: h = x @ W   (fp32).  16 rows per block, 128 threads (one per col).
// ---------------------------------------------------------------------------
__global__ void gemm_h_kernel(const float* __restrict__ x,
                              const float* __restrict__ W) {
    __shared__ float xs[16 * Fn];
    const int f = threadIdx.x;
    const long row0 = (long)blockIdx.x * 16;

    #pragma unroll
    for (int r = 0; r < 16; r++)
        xs[r * Fn + f] = x[(row0 + r) * Fn + f];
    __syncthreads();

    float acc[16];
    #pragma unroll
    for (int r = 0; r < 16; r++) acc[r] = 0.0f;

    #pragma unroll 4
    for (int k = 0; k < Fn; k++) {
        const float wv = W[k * Fn + f];
        #pragma unroll
        for (int r = 0; r < 16; r++)
            acc[r] = fmaf(xs[r * Fn + k], wv, acc[r]);
    }

    #pragma unroll
    for (int r = 0; r < 16; r++)
        g_h[(row0 + r) * Fn + f] = acc[r];
}

// ---------------------------------------------------------------------------
// Kernel 2: build deterministic per-row neighbor lists from adj (+ self loop).
// One warp per row; ballot-ordered -> fully deterministic list order.
// ---------------------------------------------------------------------------
__global__ void adj_scan_kernel(const float* __restrict__ adj) {
    const int warp = (blockIdx.x * blockDim.x + threadIdx.x) >> 5;
    const int lane = threadIdx.x & 31;
    if (warp >= Nn) return;
    const float* arow = adj + (long)warp * Nn;
    int cnt = 0;
    for (int j0 = 0; j0 < Nn; j0 += 32) {
        const int j = j0 + lane;
        const bool pred = (arow[j] != 0.0f) || (j == warp);
        const unsigned m = __ballot_sync(0xffffffffu, pred);
        if (pred) {
            const int pos = cnt + __popc(m & ((1u << lane) - 1u));
            if (pos < MAXNBR) g_nbr[warp * MAXNBR + pos] = j;
        }
        cnt += __popc(m);
    }
    if (lane == 0) g_cnt[warp] = (cnt < MAXNBR) ? cnt : MAXNBR;
}

// ---------------------------------------------------------------------------
// Kernel 3: e_src[b,i] = h[b,i,:].a_src ; e_dst likewise. One warp per row.
// ---------------------------------------------------------------------------
__global__ void srcdst_kernel(const float* __restrict__ a_src,
                              const float* __restrict__ a_dst) {
    const int warp = (blockIdx.x * blockDim.x + threadIdx.x) >> 5;  // = b*Nn+i
    const int lane = threadIdx.x & 31;
    const float* hr = g_h + (long)warp * Fn;
    float s = 0.0f, d = 0.0f;
    #pragma unroll
    for (int f = lane; f < Fn; f += 32) {
        const float hv = hr[f];
        s = fmaf(hv, a_src[f], s);
        d = fmaf(hv, a_dst[f], d);
    }
    #pragma unroll
    for (int o = 16; o; o >>= 1) {
        s += __shfl_xor_sync(0xffffffffu, s, o);
        d += __shfl_xor_sync(0xffffffffu, d, o);
    }
    if (lane == 0) { g_esrc[warp] = s; g_edst[warp] = d; }
}

// ---------------------------------------------------------------------------
// Block reduction helper (128 threads = 4 warps)
// ---------------------------------------------------------------------------
__device__ __forceinline__ float block_reduce(float v, bool is_max, float* sbuf) {
    const int lane = threadIdx.x & 31, w = threadIdx.x >> 5;
    #pragma unroll
    for (int o = 16; o; o >>= 1) {
        const float t = __shfl_xor_sync(0xffffffffu, v, o);
        v = is_max ? fmaxf(v, t) : v + t;
    }
    if (lane == 0) sbuf[w] = v;
    __syncthreads();
    if (w == 0) {
        float t = sbuf[lane & 3];
        #pragma unroll
        for (int o = 2; o; o >>= 1) {
            const float u = __shfl_xor_sync(0xffffffffu, t, o);
            t = is_max ? fmaxf(t, u) : t + u;
        }
        if (lane == 0) sbuf[0] = t;
    }
    __syncthreads();
    const float r = sbuf[0];
    __syncthreads();
    return r;
}

// ---------------------------------------------------------------------------
// Kernel 4: fused sparse softmax + aggregation + ELU.
// Block = 128 threads (one per feature), grid = (Nn, Bn).
// ---------------------------------------------------------------------------
__global__ void agg_kernel(float* __restrict__ out) {
    const int i = blockIdx.x, b = blockIdx.y;
    const int tid = threadIdx.x;

    __shared__ float p[MAXNBR];
    __shared__ int   jj[MAXNBR];
    __shared__ float sbuf[4];

    const int cnt = g_cnt[i];
    const float si = g_esrc[(long)b * Nn + i];

    // Phase 1: raw logits = leakyrelu(s_i + d_j) for kept edges only.
    for (int n = tid; n < cnt; n += 128) {
        const int j = g_nbr[i * MAXNBR + n];
        jj[n] = j;
        float v = si + g_edst[(long)b * Nn + j];
        v = (v >= 0.0f) ? v : 0.2f * v;
        p[n] = v;
    }
    __syncthreads();

    // Online-exact softmax over the cnt kept entries (all masked entries
    // contribute exp(-1e9-m) == 0.0f exactly, same as the dense reference).
    float m = -3.4e38f;
    for (int n = tid; n < cnt; n += 128) m = fmaxf(m, p[n]);
    m = block_reduce(m, true, sbuf);

    float ssum = 0.0f;
    for (int n = tid; n < cnt; n += 128) {
        const float e = expf(p[n] - m);
        p[n] = e;
        ssum += e;
    }
    ssum = block_reduce(ssum, false, sbuf);
    const float inv = 1.0f / ssum;

    // Phase 2: out[b,i,f] = elu( sum_n p[n] * h[b, jj[n], f] / ssum )
    const float* hb = g_h + (long)b * Nn * Fn;
    float a0 = 0.0f, a1 = 0.0f, a2 = 0.0f, a3 = 0.0f;
    int n = 0;
    for (; n + 3 < cnt; n += 4) {
        const float p0 = p[n], p1 = p[n + 1], p2 = p[n + 2], p3 = p[n + 3];
        const float h0 = hb[(long)jj[n]     * Fn + tid];
        const float h1 = hb[(long)jj[n + 1] * Fn + tid];
        const float h2 = hb[(long)jj[n + 2] * Fn + tid];
        const float h3 = hb[(long)jj[n + 3] * Fn + tid];
        a0 = fmaf(p0, h0, a0);
        a1 = fmaf(p1, h1, a1);
        a2 = fmaf(p2, h2, a2);
        a3 = fmaf(p3, h3, a3);
    }
    for (; n < cnt; n++)
        a0 = fmaf(p[n], hb[(long)jj[n] * Fn + tid], a0);

    float acc = ((a0 + a1) + (a2 + a3)) * inv;
    acc = (acc > 0.0f) ? acc : (expf(acc) - 1.0f);
    out[((long)b * Nn + i) * Fn + tid] = acc;
}

// ---------------------------------------------------------------------------
extern "C" void kernel_launch(void* const* d_in, const int* in_sizes, int n_in,
                              void* d_out, int out_size) {
    const float* x     = (const float*)d_in[0];   // [8, 2048, 128]
    const float* adj   = (const float*)d_in[1];   // [2048, 2048]
    const float* W     = (const float*)d_in[2];   // [128, 128]
    const float* a_src = (const float*)d_in[3];   // [128, 1]
    const float* a_dst = (const float*)d_in[4];   // [128, 1]
    float* out = (float*)d_out;                   // [8, 2048, 128]

    (void)in_sizes; (void)n_in; (void)out_size;

    // 1) h = x @ W
    gemm_h_kernel<<<(Bn * Nn) / 16, 128>>>(x, W);

    // 2) neighbor lists from adjacency (independent of kernel 1; same stream)
    adj_scan_kernel<<<(Nn * 32) / 128, 128>>>(adj);

    // 3) e_src / e_dst
    srcdst_kernel<<<(Bn * Nn * 32) / 128, 128>>>(a_src, a_dst);

    // 4) fused sparse softmax + aggregation + ELU
    dim3 grid(Nn, Bn);
    agg_kernel<<<grid, 128>>>(out);
}

// round 3
// speedup vs baseline: 1.4970x; 1.4970x over previous
#include <cuda_runtime.h>
#include <math.h>

#define Bn 8
#define Nn 2048
#define Fn 128
#define MAXNBR 256

// Scratch (allocation-free rule: __device__ globals)
__device__ __align__(16) float g_h[Bn * Nn * Fn];   // 8 MB
__device__ float g_esrc[Bn * Nn];
__device__ float g_edst[Bn * Nn];
__device__ int   g_nbr[Nn * MAXNBR];                // 2 MB
__device__ int   g_cnt[Nn];

// ---------------------------------------------------------------------------
// Kernel A (fused): blocks [0,256)  : h = x @ W  (64x128 tile) + e_src/e_dst
//                   blocks [256,512): adjacency -> neighbor lists (1 warp/row)
// ---------------------------------------------------------------------------
__global__ __launch_bounds__(256) void fused_front_kernel(
    const float* __restrict__ x,
    const float* __restrict__ adj,
    const float* __restrict__ W,
    const float* __restrict__ a_src,
    const float* __restrict__ a_dst) {

    __shared__ float xs[64 * Fn];   // 32 KB x tile

    const int bid = blockIdx.x;
    const int tid = threadIdx.x;

    if (bid < 256) {
        // ------------------ GEMM part ------------------
        const int c  = tid & 31;    // col group: cols 4c..4c+3
        const int rg = tid >> 5;    // row group: rows 8rg..8rg+7 (warp id)
        const long row0 = (long)bid * 64;

        // Load x tile [64,128] via float4, coalesced.
        const float4* x4 = (const float4*)(x + row0 * Fn);
        float4* xs4 = (float4*)xs;
        #pragma unroll
        for (int i = 0; i < 8; i++)
            xs4[tid + i * 256] = x4[tid + i * 256];
        __syncthreads();

        const float4* W4 = (const float4*)W;   // W[k][4c] = W4[k*32+c]

        float4 acc[8];
        #pragma unroll
        for (int r = 0; r < 8; r++) acc[r] = make_float4(0.f, 0.f, 0.f, 0.f);

        #pragma unroll 4
        for (int k = 0; k < Fn; k++) {
            const float4 wv = __ldg(&W4[k * 32 + c]);
            #pragma unroll
            for (int r = 0; r < 8; r++) {
                const float xv = xs[(rg * 8 + r) * Fn + k];
                acc[r].x = fmaf(xv, wv.x, acc[r].x);
                acc[r].y = fmaf(xv, wv.y, acc[r].y);
                acc[r].z = fmaf(xv, wv.z, acc[r].z);
                acc[r].w = fmaf(xv, wv.w, acc[r].w);
            }
        }

        // Epilogue: write h; fused e_src / e_dst (reduce over 32 lanes = 128 cols)
        const float4 as = ((const float4*)a_src)[c];
        const float4 ad = ((const float4*)a_dst)[c];
        float4* h4 = (float4*)g_h;

        #pragma unroll
        for (int r = 0; r < 8; r++) {
            const long row = row0 + rg * 8 + r;
            h4[row * 32 + c] = acc[r];
            float s = acc[r].x * as.x + acc[r].y * as.y + acc[r].z * as.z + acc[r].w * as.w;
            float d = acc[r].x * ad.x + acc[r].y * ad.y + acc[r].z * ad.z + acc[r].w * ad.w;
            #pragma unroll
            for (int o = 16; o; o >>= 1) {
                s += __shfl_xor_sync(0xffffffffu, s, o);
                d += __shfl_xor_sync(0xffffffffu, d, o);
            }
            if (c == 0) { g_esrc[row] = s; g_edst[row] = d; }
        }
    } else {
        // ------------------ adjacency scan part ------------------
        const int row  = ((bid - 256) << 3) + (tid >> 5);
        const int lane = tid & 31;
        const float* arow = adj + (long)row * Nn;
        int cnt = 0;
        for (int j0 = 0; j0 < Nn; j0 += 32) {
            const int j = j0 + lane;
            const bool pred = (arow[j] != 0.0f) || (j == row);
            const unsigned m = __ballot_sync(0xffffffffu, pred);
            if (pred) {
                const int pos = cnt + __popc(m & ((1u << lane) - 1u));
                if (pos < MAXNBR) g_nbr[row * MAXNBR + pos] = j;
            }
            cnt += __popc(m);
        }
        if (lane == 0) g_cnt[row] = (cnt < MAXNBR) ? cnt : MAXNBR;
    }
}

// ---------------------------------------------------------------------------
// Block reduction helper (128 threads = 4 warps)
// ---------------------------------------------------------------------------
__device__ __forceinline__ float block_reduce(float v, bool is_max, float* sbuf) {
    const int lane = threadIdx.x & 31, w = threadIdx.x >> 5;
    #pragma unroll
    for (int o = 16; o; o >>= 1) {
        const float t = __shfl_xor_sync(0xffffffffu, v, o);
        v = is_max ? fmaxf(v, t) : v + t;
    }
    if (lane == 0) sbuf[w] = v;
    __syncthreads();
    if (w == 0) {
        float t = sbuf[lane & 3];
        #pragma unroll
        for (int o = 2; o; o >>= 1) {
            const float u = __shfl_xor_sync(0xffffffffu, t, o);
            t = is_max ? fmaxf(t, u) : t + u;
        }
        if (lane == 0) sbuf[0] = t;
    }
    __syncthreads();
    const float r = sbuf[0];
    __syncthreads();
    return r;
}

// ---------------------------------------------------------------------------
// Kernel B: fused sparse softmax + aggregation + ELU (vectorized gathers).
// Block = 128 threads (4 warps), grid = (Nn, Bn).
// Phase 2: warp w takes neighbors n = w, w+4, ...; lane l gathers float4
// (features 4l..4l+3). Cross-warp combine through smem.
// ---------------------------------------------------------------------------
__global__ __launch_bounds__(128) void agg_kernel(float* __restrict__ out) {
    const int i = blockIdx.x, b = blockIdx.y;
    const int tid = threadIdx.x;
    const int w = tid >> 5, l = tid & 31;

    __shared__ float p[MAXNBR];
    __shared__ int   jj[MAXNBR];
    __shared__ float sred[4 * 128];
    __shared__ float sbuf[4];

    const int cnt = g_cnt[i];
    const float si = g_esrc[(long)b * Nn + i];

    // Phase 1: logits = leakyrelu(s_i + d_j) for kept edges.
    for (int n = tid; n < cnt; n += 128) {
        const int j = g_nbr[i * MAXNBR + n];
        jj[n] = j;
        float v = si + g_edst[(long)b * Nn + j];
        v = (v >= 0.0f) ? v : 0.2f * v;
        p[n] = v;
    }
    __syncthreads();

    // Exact softmax over kept entries (masked ones are exactly 0 after exp,
    // identical to the dense reference's fp32 arithmetic).
    float m = -3.4e38f;
    for (int n = tid; n < cnt; n += 128) m = fmaxf(m, p[n]);
    m = block_reduce(m, true, sbuf);

    float ssum = 0.0f;
    for (int n = tid; n < cnt; n += 128) {
        const float e = expf(p[n] - m);
        p[n] = e;
        ssum += e;
    }
    ssum = block_reduce(ssum, false, sbuf);
    const float inv = 1.0f / ssum;

    // Phase 2: vectorized gather-accumulate.
    const float4* H4 = (const float4*)(g_h + (long)b * Nn * Fn);
    float4 acc = make_float4(0.f, 0.f, 0.f, 0.f);
    int n = w;
    for (; n + 4 < cnt; n += 8) {
        const float p0 = p[n], p1 = p[n + 4];
        const float4 h0 = H4[jj[n]     * 32 + l];
        const float4 h1 = H4[jj[n + 4] * 32 + l];
        acc.x = fmaf(p0, h0.x, acc.x);
        acc.y = fmaf(p0, h0.y, acc.y);
        acc.z = fmaf(p0, h0.z, acc.z);
        acc.w = fmaf(p0, h0.w, acc.w);
        acc.x = fmaf(p1, h1.x, acc.x);
        acc.y = fmaf(p1, h1.y, acc.y);
        acc.z = fmaf(p1, h1.z, acc.z);
        acc.w = fmaf(p1, h1.w, acc.w);
    }
    if (n < cnt) {
        const float p0 = p[n];
        const float4 h0 = H4[jj[n] * 32 + l];
        acc.x = fmaf(p0, h0.x, acc.x);
        acc.y = fmaf(p0, h0.y, acc.y);
        acc.z = fmaf(p0, h0.z, acc.z);
        acc.w = fmaf(p0, h0.w, acc.w);
    }
    ((float4*)sred)[w * 32 + l] = acc;
    __syncthreads();

    // Combine the 4 warps' partials; feature f = tid.
    float r = sred[tid] + sred[128 + tid] + sred[256 + tid] + sred[384 + tid];
    r *= inv;
    r = (r > 0.0f) ? r : (expf(r) - 1.0f);
    out[((long)b * Nn + i) * Fn + tid] = r;
}

// ---------------------------------------------------------------------------
extern "C" void kernel_launch(void* const* d_in, const int* in_sizes, int n_in,
                              void* d_out, int out_size) {
    const float* x     = (const float*)d_in[0];   // [8, 2048, 128]
    const float* adj   = (const float*)d_in[1];   // [2048, 2048]
    const float* W     = (const float*)d_in[2];   // [128, 128]
    const float* a_src = (const float*)d_in[3];   // [128, 1]
    const float* a_dst = (const float*)d_in[4];   // [128, 1]
    float* out = (float*)d_out;                   // [8, 2048, 128]
    (void)in_sizes; (void)n_in; (void)out_size;

    // 1) h = x@W + e_src/e_dst epilogue, with adjacency scan filling the tail
    fused_front_kernel<<<512, 256>>>(x, adj, W, a_src, a_dst);

    // 2) fused sparse softmax + aggregation + ELU
    dim3 grid(Nn, Bn);
    agg_kernel<<<grid, 128>>>(out);
}

// round 4
// speedup vs baseline: 1.5563x; 1.0396x over previous
#include <cuda_runtime.h>
#include <math.h>

#define Bn 8
#define Nn 2048
#define Fn 128
#define MAXNBR 256
#define FULL 0xffffffffu

// Scratch (allocation-free rule: __device__ globals)
__device__ __align__(16) float g_h[Bn * Nn * Fn];   // 8 MB
__device__ float g_esrc[Bn * Nn];
__device__ float g_edst[Bn * Nn];
__device__ int   g_nbr[Nn * MAXNBR];                // 2 MB
__device__ int   g_cnt[Nn];

// packed dual-fp32 FMA (PTX-only on sm_103a; ptxas never emits FFMA2 itself)
__device__ __forceinline__ void fma2(unsigned long long& d,
                                     unsigned long long a,
                                     unsigned long long b) {
    asm("fma.rn.f32x2 %0, %1, %2, %0;" : "+l"(d) : "l"(a), "l"(b));
}
__device__ __forceinline__ unsigned long long pack2(float v) {
    unsigned long long r;
    asm("mov.b64 %0, {%1, %1};" : "=l"(r) : "f"(v));
    return r;
}
__device__ __forceinline__ void unpack2(unsigned long long p, float& a, float& b) {
    asm("mov.b64 {%0, %1}, %2;" : "=f"(a), "=f"(b) : "l"(p));
}

// ---------------------------------------------------------------------------
// Kernel A (fused): blocks [0,256)  : h = x @ W (64x128 tile, f32x2 FMA)
//                                     + fused e_src/e_dst epilogue
//                   blocks [256,512): adjacency -> neighbor lists
//                                     (1 warp/row, float4 + prefix scan)
// ---------------------------------------------------------------------------
__global__ __launch_bounds__(256) void fused_front_kernel(
    const float* __restrict__ x,
    const float* __restrict__ adj,
    const float* __restrict__ W,
    const float* __restrict__ a_src,
    const float* __restrict__ a_dst) {

    __shared__ float xs[64 * Fn];   // 32 KB x tile

    const int bid = blockIdx.x;
    const int tid = threadIdx.x;

    if (bid < 256) {
        // ------------------ GEMM part ------------------
        const int c  = tid & 31;    // col group: cols 4c..4c+3
        const int rg = tid >> 5;    // row group: rows 8rg..8rg+7 (warp id)
        const long row0 = (long)bid * 64;

        // Load x tile [64,128] via float4, coalesced.
        const float4* x4 = (const float4*)(x + row0 * Fn);
        float4* xs4 = (float4*)xs;
        #pragma unroll
        for (int i = 0; i < 8; i++)
            xs4[tid + i * 256] = x4[tid + i * 256];
        __syncthreads();

        // W viewed as packed col-pairs: W2[k*32+c] = cols (4c,4c+1),(4c+2,4c+3)
        const ulonglong2* W2 = (const ulonglong2*)W;

        unsigned long long acc[8][2];
        #pragma unroll
        for (int r = 0; r < 8; r++) { acc[r][0] = 0ull; acc[r][1] = 0ull; }

        #pragma unroll 4
        for (int k = 0; k < Fn; k++) {
            const ulonglong2 wv = W2[k * 32 + c];
            #pragma unroll
            for (int r = 0; r < 8; r++) {
                const unsigned long long xv2 = pack2(xs[(rg * 8 + r) * Fn + k]);
                fma2(acc[r][0], xv2, wv.x);
                fma2(acc[r][1], xv2, wv.y);
            }
        }

        // Epilogue: write h; fused e_src / e_dst (reduce over 32 lanes)
        const float4 as = ((const float4*)a_src)[c];
        const float4 ad = ((const float4*)a_dst)[c];
        float4* h4 = (float4*)g_h;

        #pragma unroll
        for (int r = 0; r < 8; r++) {
            const long row = row0 + rg * 8 + r;
            float4 hv;
            unpack2(acc[r][0], hv.x, hv.y);
            unpack2(acc[r][1], hv.z, hv.w);
            h4[row * 32 + c] = hv;
            float s = hv.x * as.x + hv.y * as.y + hv.z * as.z + hv.w * as.w;
            float d = hv.x * ad.x + hv.y * ad.y + hv.z * ad.z + hv.w * ad.w;
            #pragma unroll
            for (int o = 16; o; o >>= 1) {
                s += __shfl_xor_sync(FULL, s, o);
                d += __shfl_xor_sync(FULL, d, o);
            }
            if (c == 0) { g_esrc[row] = s; g_edst[row] = d; }
        }
    } else {
        // ------------------ adjacency scan part ------------------
        // 1 warp per row; lane reads float4 -> 4-bit mask -> warp prefix scan.
        // Order: lane l covers j = j0+4l..4l+3, lanes ascending => global
        // ascending neighbor order (deterministic).
        const int row  = ((bid - 256) << 3) + (tid >> 5);
        const int lane = tid & 31;
        const float4* arow = (const float4*)(adj + (long)row * Nn);
        int cnt = 0;
        #pragma unroll 2
        for (int it = 0; it < Nn / 128; it++) {
            const int j0 = it * 128 + lane * 4;
            const float4 v = arow[it * 32 + lane];
            unsigned msk = 0;
            if (v.x != 0.0f || j0     == row) msk |= 1;
            if (v.y != 0.0f || j0 + 1 == row) msk |= 2;
            if (v.z != 0.0f || j0 + 2 == row) msk |= 4;
            if (v.w != 0.0f || j0 + 3 == row) msk |= 8;
            const int cme = __popc(msk);
            // inclusive prefix sum over lanes
            int pref = cme;
            #pragma unroll
            for (int o = 1; o < 32; o <<= 1) {
                const int t = __shfl_up_sync(FULL, pref, o);
                if (lane >= o) pref += t;
            }
            int pos = cnt + pref - cme;       // exclusive base for this lane
            const int total = __shfl_sync(FULL, pref, 31);
            if (msk & 1) { if (pos < MAXNBR) g_nbr[row * MAXNBR + pos] = j0;     pos++; }
            if (msk & 2) { if (pos < MAXNBR) g_nbr[row * MAXNBR + pos] = j0 + 1; pos++; }
            if (msk & 4) { if (pos < MAXNBR) g_nbr[row * MAXNBR + pos] = j0 + 2; pos++; }
            if (msk & 8) { if (pos < MAXNBR) g_nbr[row * MAXNBR + pos] = j0 + 3; pos++; }
            cnt += total;
        }
        if (lane == 0) g_cnt[row] = (cnt < MAXNBR) ? cnt : MAXNBR;
    }
}

// ---------------------------------------------------------------------------
// Kernel B: fused sparse softmax + aggregation + ELU.
// One WARP per (b,i): softmax via shuffles (no barriers); each neighbor's
// (exp-logit, row-offset) packed as float2 in smem; gather loop does one
// broadcast LDS.64 + one LDG.128 per neighbor per lane (lane = 4 features).
// ---------------------------------------------------------------------------
__global__ __launch_bounds__(128) void agg_kernel(float* __restrict__ out) {
    const int w = threadIdx.x >> 5, lane = threadIdx.x & 31;
    const int gw = blockIdx.x * 4 + w;          // [0, 16384)
    const int b = gw >> 11, i = gw & (Nn - 1);

    __shared__ float2 pj_s[4][MAXNBR];
    float2* pj = pj_s[w];

    const int cnt = g_cnt[i];
    const float si = g_esrc[(long)b * Nn + i];
    const float* edst = g_edst + (long)b * Nn;

    // Phase 1: logits = leakyrelu(s_i + d_j); track max.
    float m = -3.4e38f;
    for (int n = lane; n < cnt; n += 32) {
        const int j = g_nbr[i * MAXNBR + n];
        float v = si + edst[j];
        v = (v >= 0.0f) ? v : 0.2f * v;
        pj[n] = make_float2(v, __int_as_float(j << 5));   // j*32 float4-row offset
        m = fmaxf(m, v);
    }
    #pragma unroll
    for (int o = 16; o; o >>= 1) m = fmaxf(m, __shfl_xor_sync(FULL, m, o));
    __syncwarp();

    // exp + sum (masked entries are exactly 0 after exp, matching the dense ref)
    float s = 0.0f;
    for (int n = lane; n < cnt; n += 32) {
        const float e = expf(pj[n].x - m);
        pj[n].x = e;
        s += e;
    }
    #pragma unroll
    for (int o = 16; o; o >>= 1) s += __shfl_xor_sync(FULL, s, o);
    const float inv = 1.0f / s;
    __syncwarp();

    // Phase 2: gather-accumulate. lane covers features 4*lane..4*lane+3.
    const float4* Hb = (const float4*)g_h + (long)b * Nn * 32;
    float4 a0 = {0,0,0,0}, a1 = {0,0,0,0}, a2 = {0,0,0,0}, a3 = {0,0,0,0};
    int n = 0;
    for (; n + 4 <= cnt; n += 4) {
        const float2 t0 = pj[n], t1 = pj[n+1], t2 = pj[n+2], t3 = pj[n+3];
        const float4 h0 = Hb[__float_as_int(t0.y) + lane];
        const float4 h1 = Hb[__float_as_int(t1.y) + lane];
        const float4 h2 = Hb[__float_as_int(t2.y) + lane];
        const float4 h3 = Hb[__float_as_int(t3.y) + lane];
        a0.x = fmaf(t0.x, h0.x, a0.x); a0.y = fmaf(t0.x, h0.y, a0.y);
        a0.z = fmaf(t0.x, h0.z, a0.z); a0.w = fmaf(t0.x, h0.w, a0.w);
        a1.x = fmaf(t1.x, h1.x, a1.x); a1.y = fmaf(t1.x, h1.y, a1.y);
        a1.z = fmaf(t1.x, h1.z, a1.z); a1.w = fmaf(t1.x, h1.w, a1.w);
        a2.x = fmaf(t2.x, h2.x, a2.x); a2.y = fmaf(t2.x, h2.y, a2.y);
        a2.z = fmaf(t2.x, h2.z, a2.z); a2.w = fmaf(t2.x, h2.w, a2.w);
        a3.x = fmaf(t3.x, h3.x, a3.x); a3.y = fmaf(t3.x, h3.y, a3.y);
        a3.z = fmaf(t3.x, h3.z, a3.z); a3.w = fmaf(t3.x, h3.w, a3.w);
    }
    for (; n < cnt; n++) {
        const float2 t = pj[n];
        const float4 h0 = Hb[__float_as_int(t.y) + lane];
        a0.x = fmaf(t.x, h0.x, a0.x); a0.y = fmaf(t.x, h0.y, a0.y);
        a0.z = fmaf(t.x, h0.z, a0.z); a0.w = fmaf(t.x, h0.w, a0.w);
    }

    float4 r;
    r.x = ((a0.x + a1.x) + (a2.x + a3.x)) * inv;
    r.y = ((a0.y + a1.y) + (a2.y + a3.y)) * inv;
    r.z = ((a0.z + a1.z) + (a2.z + a3.z)) * inv;
    r.w = ((a0.w + a1.w) + (a2.w + a3.w)) * inv;
    r.x = (r.x > 0.0f) ? r.x : (expf(r.x) - 1.0f);
    r.y = (r.y > 0.0f) ? r.y : (expf(r.y) - 1.0f);
    r.z = (r.z > 0.0f) ? r.z : (expf(r.z) - 1.0f);
    r.w = (r.w > 0.0f) ? r.w : (expf(r.w) - 1.0f);
    ((float4*)out)[((long)b * Nn + i) * 32 + lane] = r;
}

// ---------------------------------------------------------------------------
extern "C" void kernel_launch(void* const* d_in, const int* in_sizes, int n_in,
                              void* d_out, int out_size) {
    const float* x     = (const float*)d_in[0];   // [8, 2048, 128]
    const float* adj   = (const float*)d_in[1];   // [2048, 2048]
    const float* W     = (const float*)d_in[2];   // [128, 128]
    const float* a_src = (const float*)d_in[3];   // [128, 1]
    const float* a_dst = (const float*)d_in[4];   // [128, 1]
    float* out = (float*)d_out;                   // [8, 2048, 128]
    (void)in_sizes; (void)n_in; (void)out_size;

    // 1) h = x@W (+e_src/e_dst epilogue) with adjacency scan in the tail wave
    fused_front_kernel<<<512, 256>>>(x, adj, W, a_src, a_dst);

    // 2) fused sparse softmax + aggregation + ELU (warp per (b,i))
    agg_kernel<<<Bn * Nn / 4, 128>>>(out);
}

// round 8
// speedup vs baseline: 1.6215x; 1.0419x over previous
#include <cuda_runtime.h>
#include <cuda_fp16.h>
#include <math.h>

#define Bn 8
#define Nn 2048
#define Fn 128
#define MAXNBR 256
#define FULL 0xffffffffu

// Scratch (allocation-free rule: __device__ globals)
__device__ __align__(16) __half2 g_hh[Bn * Nn * Fn / 2];  // 4 MB fp16 h
__device__ float g_esrc[Bn * Nn];
__device__ float g_edst[Bn * Nn];
__device__ int   g_nbr[Nn * MAXNBR];                      // 2 MB
__device__ int   g_cnt[Nn];

// packed dual-fp32 FMA (PTX-only on sm_103a)
__device__ __forceinline__ void fma2(unsigned long long& d,
                                     unsigned long long a,
                                     unsigned long long b) {
    asm("fma.rn.f32x2 %0, %1, %2, %0;" : "+l"(d) : "l"(a), "l"(b));
}
__device__ __forceinline__ unsigned long long pack2(float v) {
    unsigned long long r;
    asm("mov.b64 %0, {%1, %1};" : "=l"(r) : "f"(v));
    return r;
}
__device__ __forceinline__ void unpack2(unsigned long long p, float& a, float& b) {
    asm("mov.b64 {%0, %1}, %2;" : "=f"(a), "=f"(b) : "l"(p));
}

// ---------------------------------------------------------------------------
// Kernel A (fused): blocks [0,256)  : h = x @ W (64x128 tile, f32x2 FMA,
//                                     LDS.128 x-caching) + e_src/e_dst epilogue,
//                                     h written as fp16
//                   blocks [256,512): adjacency -> neighbor lists
// ---------------------------------------------------------------------------
__global__ __launch_bounds__(256) void fused_front_kernel(
    const float* __restrict__ x,
    const float* __restrict__ adj,
    const float* __restrict__ W,
    const float* __restrict__ a_src,
    const float* __restrict__ a_dst) {

    __shared__ float xs[64 * Fn];   // 32 KB x tile

    const int bid = blockIdx.x;
    const int tid = threadIdx.x;

    if (bid < 256) {
        // ------------------ GEMM part ------------------
        const int c  = tid & 31;    // col group: cols 4c..4c+3
        const int rg = tid >> 5;    // row group: rows 8rg..8rg+7
        const long row0 = (long)bid * 64;

        const float4* x4 = (const float4*)(x + row0 * Fn);
        float4* xs4 = (float4*)xs;
        #pragma unroll
        for (int i = 0; i < 8; i++)
            xs4[tid + i * 256] = x4[tid + i * 256];
        __syncthreads();

        // W as packed col-pairs: W2[k*32+c] = cols (4c,4c+1),(4c+2,4c+3)
        const ulonglong2* W2 = (const ulonglong2*)W;

        unsigned long long acc[8][2];
        #pragma unroll
        for (int r = 0; r < 8; r++) { acc[r][0] = 0ull; acc[r][1] = 0ull; }

        #pragma unroll 2
        for (int k4 = 0; k4 < Fn / 4; k4++) {
            float4 xv[8];
            #pragma unroll
            for (int r = 0; r < 8; r++)
                xv[r] = xs4[(rg * 8 + r) * 32 + k4];
            #pragma unroll
            for (int kk = 0; kk < 4; kk++) {
                const ulonglong2 wv = W2[(k4 * 4 + kk) * 32 + c];
                #pragma unroll
                for (int r = 0; r < 8; r++) {
                    const float xe = (kk == 0) ? xv[r].x :
                                     (kk == 1) ? xv[r].y :
                                     (kk == 2) ? xv[r].z : xv[r].w;
                    const unsigned long long xv2 = pack2(xe);
                    fma2(acc[r][0], xv2, wv.x);
                    fma2(acc[r][1], xv2, wv.y);
                }
            }
        }

        // Epilogue: e_src/e_dst from fp32 regs; h stored fp16.
        const float4 as = ((const float4*)a_src)[c];
        const float4 ad = ((const float4*)a_dst)[c];
        uint2* hh = (uint2*)g_hh;   // 8B = 4 fp16 features

        #pragma unroll
        for (int r = 0; r < 8; r++) {
            const long row = row0 + rg * 8 + r;
            float4 hv;
            unpack2(acc[r][0], hv.x, hv.y);
            unpack2(acc[r][1], hv.z, hv.w);
            const __half2 h01 = __floats2half2_rn(hv.x, hv.y);
            const __half2 h23 = __floats2half2_rn(hv.z, hv.w);
            uint2 packed;
            packed.x = *(const unsigned*)&h01;
            packed.y = *(const unsigned*)&h23;
            hh[row * 32 + c] = packed;
            float s = hv.x * as.x + hv.y * as.y + hv.z * as.z + hv.w * as.w;
            float d = hv.x * ad.x + hv.y * ad.y + hv.z * ad.z + hv.w * ad.w;
            #pragma unroll
            for (int o = 16; o; o >>= 1) {
                s += __shfl_xor_sync(FULL, s, o);
                d += __shfl_xor_sync(FULL, d, o);
            }
            if (c == 0) { g_esrc[row] = s; g_edst[row] = d; }
        }
    } else {
        // ------------------ adjacency scan part ------------------
        const int row  = ((bid - 256) << 3) + (tid >> 5);
        const int lane = tid & 31;
        const float4* arow = (const float4*)(adj + (long)row * Nn);
        int cnt = 0;
        #pragma unroll 2
        for (int it = 0; it < Nn / 128; it++) {
            const int j0 = it * 128 + lane * 4;
            const float4 v = arow[it * 32 + lane];
            unsigned msk = 0;
            if (v.x != 0.0f || j0     == row) msk |= 1;
            if (v.y != 0.0f || j0 + 1 == row) msk |= 2;
            if (v.z != 0.0f || j0 + 2 == row) msk |= 4;
            if (v.w != 0.0f || j0 + 3 == row) msk |= 8;
            const int cme = __popc(msk);
            int pref = cme;
            #pragma unroll
            for (int o = 1; o < 32; o <<= 1) {
                const int t = __shfl_up_sync(FULL, pref, o);
                if (lane >= o) pref += t;
            }
            int pos = cnt + pref - cme;
            const int total = __shfl_sync(FULL, pref, 31);
            if (msk & 1) { if (pos < MAXNBR) g_nbr[row * MAXNBR + pos] = j0;     pos++; }
            if (msk & 2) { if (pos < MAXNBR) g_nbr[row * MAXNBR + pos] = j0 + 1; pos++; }
            if (msk & 4) { if (pos < MAXNBR) g_nbr[row * MAXNBR + pos] = j0 + 2; pos++; }
            if (msk & 8) { if (pos < MAXNBR) g_nbr[row * MAXNBR + pos] = j0 + 3; pos++; }
            cnt += total;
        }
        if (lane == 0) g_cnt[row] = (cnt < MAXNBR) ? cnt : MAXNBR;
    }
}

// ---------------------------------------------------------------------------
// Kernel B: fused sparse softmax + aggregation + ELU.
// One WARP per (b,i); softmax via shuffles; fp16 h gathers (LDG.64/lane,
// 256 B per neighbor), fp32 accumulate.
// ---------------------------------------------------------------------------
__global__ __launch_bounds__(128) void agg_kernel(float* __restrict__ out) {
    const int w = threadIdx.x >> 5, lane = threadIdx.x & 31;
    const int gw = blockIdx.x * 4 + w;          // [0, 16384)
    const int b = gw >> 11, i = gw & (Nn - 1);

    __shared__ float2 pj_s[4][MAXNBR];
    float2* pj = pj_s[w];

    const int cnt = g_cnt[i];
    const float si = g_esrc[(long)b * Nn + i];
    const float* edst = g_edst + (long)b * Nn;

    // Phase 1: logits = leakyrelu(s_i + d_j); track max.
    float m = -3.4e38f;
    for (int n = lane; n < cnt; n += 32) {
        const int j = g_nbr[i * MAXNBR + n];
        float v = si + edst[j];
        v = (v >= 0.0f) ? v : 0.2f * v;
        pj[n] = make_float2(v, __int_as_float(j << 5));   // j*32 uint2-row offset
        m = fmaxf(m, v);
    }
    #pragma unroll
    for (int o = 16; o; o >>= 1) m = fmaxf(m, __shfl_xor_sync(FULL, m, o));
    __syncwarp();

    float s = 0.0f;
    for (int n = lane; n < cnt; n += 32) {
        const float e = expf(pj[n].x - m);
        pj[n].x = e;
        s += e;
    }
    #pragma unroll
    for (int o = 16; o; o >>= 1) s += __shfl_xor_sync(FULL, s, o);
    const float inv = 1.0f / s;
    __syncwarp();

    // Phase 2: fp16 gather-accumulate. lane covers features 4*lane..4*lane+3.
    const uint2* Hb = (const uint2*)g_hh + (long)b * Nn * 32;
    float4 a0 = {0,0,0,0}, a1 = {0,0,0,0}, a2 = {0,0,0,0}, a3 = {0,0,0,0};
    int n = 0;
    for (; n + 4 <= cnt; n += 4) {
        const float2 t0 = pj[n], t1 = pj[n+1], t2 = pj[n+2], t3 = pj[n+3];
        const uint2 r0 = Hb[__float_as_int(t0.y) + lane];
        const uint2 r1 = Hb[__float_as_int(t1.y) + lane];
        const uint2 r2 = Hb[__float_as_int(t2.y) + lane];
        const uint2 r3 = Hb[__float_as_int(t3.y) + lane];
        const float2 h0a = __half22float2(*(const __half2*)&r0.x);
        const float2 h0b = __half22float2(*(const __half2*)&r0.y);
        const float2 h1a = __half22float2(*(const __half2*)&r1.x);
        const float2 h1b = __half22float2(*(const __half2*)&r1.y);
        const float2 h2a = __half22float2(*(const __half2*)&r2.x);
        const float2 h2b = __half22float2(*(const __half2*)&r2.y);
        const float2 h3a = __half22float2(*(const __half2*)&r3.x);
        const float2 h3b = __half22float2(*(const __half2*)&r3.y);
        a0.x = fmaf(t0.x, h0a.x, a0.x); a0.y = fmaf(t0.x, h0a.y, a0.y);
        a0.z = fmaf(t0.x, h0b.x, a0.z); a0.w = fmaf(t0.x, h0b.y, a0.w);
        a1.x = fmaf(t1.x, h1a.x, a1.x); a1.y = fmaf(t1.x, h1a.y, a1.y);
        a1.z = fmaf(t1.x, h1b.x, a1.z); a1.w = fmaf(t1.x, h1b.y, a1.w);
        a2.x = fmaf(t2.x, h2a.x, a2.x); a2.y = fmaf(t2.x, h2a.y, a2.y);
        a2.z = fmaf(t2.x, h2b.x, a2.z); a2.w = fmaf(t2.x, h2b.y, a2.w);
        a3.x = fmaf(t3.x, h3a.x, a3.x); a3.y = fmaf(t3.x, h3a.y, a3.y);
        a3.z = fmaf(t3.x, h3b.x, a3.z); a3.w = fmaf(t3.x, h3b.y, a3.w);
    }
    for (; n < cnt; n++) {
        const float2 t = pj[n];
        const uint2 r0 = Hb[__float_as_int(t.y) + lane];
        const float2 h0a = __half22float2(*(const __half2*)&r0.x);
        const float2 h0b = __half22float2(*(const __half2*)&r0.y);
        a0.x = fmaf(t.x, h0a.x, a0.x); a0.y = fmaf(t.x, h0a.y, a0.y);
        a0.z = fmaf(t.x, h0b.x, a0.z); a0.w = fmaf(t.x, h0b.y, a0.w);
    }

    float4 r;
    r.x = ((a0.x + a1.x) + (a2.x + a3.x)) * inv;
    r.y = ((a0.y + a1.y) + (a2.y + a3.y)) * inv;
    r.z = ((a0.z + a1.z) + (a2.z + a3.z)) * inv;
    r.w = ((a0.w + a1.w) + (a2.w + a3.w)) * inv;
    r.x = (r.x > 0.0f) ? r.x : (expf(r.x) - 1.0f);
    r.y = (r.y > 0.0f) ? r.y : (expf(r.y) - 1.0f);
    r.z = (r.z > 0.0f) ? r.z : (expf(r.z) - 1.0f);
    r.w = (r.w > 0.0f) ? r.w : (expf(r.w) - 1.0f);
    ((float4*)out)[((long)b * Nn + i) * 32 + lane] = r;
}

// ---------------------------------------------------------------------------
extern "C" void kernel_launch(void* const* d_in, const int* in_sizes, int n_in,
                              void* d_out, int out_size) {
    const float* x     = (const float*)d_in[0];   // [8, 2048, 128]
    const float* adj   = (const float*)d_in[1];   // [2048, 2048]
    const float* W     = (const float*)d_in[2];   // [128, 128]
    const float* a_src = (const float*)d_in[3];   // [128, 1]
    const float* a_dst = (const float*)d_in[4];   // [128, 1]
    float* out = (float*)d_out;                   // [8, 2048, 128]
    (void)in_sizes; (void)n_in; (void)out_size;

    fused_front_kernel<<<512, 256>>>(x, adj, W, a_src, a_dst);
    agg_kernel<<<Bn * Nn / 4, 128>>>(out);
}

// round 12
// speedup vs baseline: 1.6902x; 1.0423x over previous
#include <cuda_runtime.h>
#include <math.h>

#define Bn 8
#define Nn 2048
#define Fn 128
#define MAXNBR 256
#define FULL 0xffffffffu

// Scratch (allocation-free rule: __device__ globals)
__device__ __align__(16) float g_h[Bn * Nn * Fn];   // 8 MB fp32 h
__device__ float g_esrc[Bn * Nn];
__device__ float g_edst[Bn * Nn];
__device__ int   g_nbr[Nn * MAXNBR];                // 2 MB
__device__ int   g_cnt[Nn];

// packed dual-fp32 FMA (PTX-only on sm_103a)
__device__ __forceinline__ void fma2(unsigned long long& d,
                                     unsigned long long a,
                                     unsigned long long b) {
    asm("fma.rn.f32x2 %0, %1, %2, %0;" : "+l"(d) : "l"(a), "l"(b));
}
__device__ __forceinline__ unsigned long long pack2(float v) {
    unsigned long long r;
    asm("mov.b64 %0, {%1, %1};" : "=l"(r) : "f"(v));
    return r;
}
__device__ __forceinline__ void unpack2(unsigned long long p, float& a, float& b) {
    asm("mov.b64 {%0, %1}, %2;" : "=f"(a), "=f"(b) : "l"(p));
}

// ---------------------------------------------------------------------------
// Kernel A (fused): blocks [0,256)  : h = x @ W (64x128 tile, f32x2 FMA,
//                                     LDS.128 x-caching) + e_src/e_dst epilogue
//                   blocks [256,512): adjacency -> neighbor lists
// ---------------------------------------------------------------------------
__global__ __launch_bounds__(256) void fused_front_kernel(
    const float* __restrict__ x,
    const float* __restrict__ adj,
    const float* __restrict__ W,
    const float* __restrict__ a_src,
    const float* __restrict__ a_dst) {

    __shared__ float xs[64 * Fn];   // 32 KB x tile

    const int bid = blockIdx.x;
    const int tid = threadIdx.x;

    if (bid < 256) {
        // ------------------ GEMM part ------------------
        const int c  = tid & 31;    // col group: cols 4c..4c+3
        const int rg = tid >> 5;    // row group: rows 8rg..8rg+7
        const long row0 = (long)bid * 64;

        const float4* x4 = (const float4*)(x + row0 * Fn);
        float4* xs4 = (float4*)xs;
        #pragma unroll
        for (int i = 0; i < 8; i++)
            xs4[tid + i * 256] = x4[tid + i * 256];
        __syncthreads();

        // W as packed col-pairs: W2[k*32+c] = cols (4c,4c+1),(4c+2,4c+3)
        const ulonglong2* W2 = (const ulonglong2*)W;

        unsigned long long acc[8][2];
        #pragma unroll
        for (int r = 0; r < 8; r++) { acc[r][0] = 0ull; acc[r][1] = 0ull; }

        #pragma unroll 2
        for (int k4 = 0; k4 < Fn / 4; k4++) {
            float4 xv[8];
            #pragma unroll
            for (int r = 0; r < 8; r++)
                xv[r] = xs4[(rg * 8 + r) * 32 + k4];
            #pragma unroll
            for (int kk = 0; kk < 4; kk++) {
                const ulonglong2 wv = W2[(k4 * 4 + kk) * 32 + c];
                #pragma unroll
                for (int r = 0; r < 8; r++) {
                    const float xe = (kk == 0) ? xv[r].x :
                                     (kk == 1) ? xv[r].y :
                                     (kk == 2) ? xv[r].z : xv[r].w;
                    const unsigned long long xv2 = pack2(xe);
                    fma2(acc[r][0], xv2, wv.x);
                    fma2(acc[r][1], xv2, wv.y);
                }
            }
        }

        // Epilogue: write h (fp32); fused e_src / e_dst.
        const float4 as = ((const float4*)a_src)[c];
        const float4 ad = ((const float4*)a_dst)[c];
        float4* h4 = (float4*)g_h;

        #pragma unroll
        for (int r = 0; r < 8; r++) {
            const long row = row0 + rg * 8 + r;
            float4 hv;
            unpack2(acc[r][0], hv.x, hv.y);
            unpack2(acc[r][1], hv.z, hv.w);
            h4[row * 32 + c] = hv;
            float s = hv.x * as.x + hv.y * as.y + hv.z * as.z + hv.w * as.w;
            float d = hv.x * ad.x + hv.y * ad.y + hv.z * ad.z + hv.w * ad.w;
            #pragma unroll
            for (int o = 16; o; o >>= 1) {
                s += __shfl_xor_sync(FULL, s, o);
                d += __shfl_xor_sync(FULL, d, o);
            }
            if (c == 0) { g_esrc[row] = s; g_edst[row] = d; }
        }
    } else {
        // ------------------ adjacency scan part ------------------
        const int row  = ((bid - 256) << 3) + (tid >> 5);
        const int lane = tid & 31;
        const float4* arow = (const float4*)(adj + (long)row * Nn);
        int cnt = 0;
        #pragma unroll 2
        for (int it = 0; it < Nn / 128; it++) {
            const int j0 = it * 128 + lane * 4;
            const float4 v = arow[it * 32 + lane];
            unsigned msk = 0;
            if (v.x != 0.0f || j0     == row) msk |= 1;
            if (v.y != 0.0f || j0 + 1 == row) msk |= 2;
            if (v.z != 0.0f || j0 + 2 == row) msk |= 4;
            if (v.w != 0.0f || j0 + 3 == row) msk |= 8;
            const int cme = __popc(msk);
            int pref = cme;
            #pragma unroll
            for (int o = 1; o < 32; o <<= 1) {
                const int t = __shfl_up_sync(FULL, pref, o);
                if (lane >= o) pref += t;
            }
            int pos = cnt + pref - cme;
            const int total = __shfl_sync(FULL, pref, 31);
            if (msk & 1) { if (pos < MAXNBR) g_nbr[row * MAXNBR + pos] = j0;     pos++; }
            if (msk & 2) { if (pos < MAXNBR) g_nbr[row * MAXNBR + pos] = j0 + 1; pos++; }
            if (msk & 4) { if (pos < MAXNBR) g_nbr[row * MAXNBR + pos] = j0 + 2; pos++; }
            if (msk & 8) { if (pos < MAXNBR) g_nbr[row * MAXNBR + pos] = j0 + 3; pos++; }
            cnt += total;
        }
        if (lane == 0) g_cnt[row] = (cnt < MAXNBR) ? cnt : MAXNBR;
    }
}

// ---------------------------------------------------------------------------
// Kernel B: fused sparse softmax + aggregation + ELU.
// One WARP per (b,i); softmax via shuffles; fp32 float4 gathers with
// 8-deep unroll (8 independent LDG.128 in flight per warp).
// ---------------------------------------------------------------------------
__global__ __launch_bounds__(128) void agg_kernel(float* __restrict__ out) {
    const int w = threadIdx.x >> 5, lane = threadIdx.x & 31;
    const int gw = blockIdx.x * 4 + w;          // [0, 16384)
    const int b = gw >> 11, i = gw & (Nn - 1);

    __shared__ float2 pj_s[4][MAXNBR];
    float2* pj = pj_s[w];

    const int cnt = g_cnt[i];
    const float si = g_esrc[(long)b * Nn + i];
    const float* edst = g_edst + (long)b * Nn;

    // Phase 1: logits = leakyrelu(s_i + d_j); track max.
    float m = -3.4e38f;
    for (int n = lane; n < cnt; n += 32) {
        const int j = g_nbr[i * MAXNBR + n];
        float v = si + edst[j];
        v = (v >= 0.0f) ? v : 0.2f * v;
        pj[n] = make_float2(v, __int_as_float(j << 5));   // j*32 float4-row offset
        m = fmaxf(m, v);
    }
    #pragma unroll
    for (int o = 16; o; o >>= 1) m = fmaxf(m, __shfl_xor_sync(FULL, m, o));
    __syncwarp();

    float s = 0.0f;
    for (int n = lane; n < cnt; n += 32) {
        const float e = expf(pj[n].x - m);
        pj[n].x = e;
        s += e;
    }
    #pragma unroll
    for (int o = 16; o; o >>= 1) s += __shfl_xor_sync(FULL, s, o);
    const float inv = 1.0f / s;
    __syncwarp();

    // Phase 2: gather-accumulate, 8 neighbors in flight.
    const float4* Hb = (const float4*)g_h + (long)b * Nn * 32;
    float4 acc[4];
    #pragma unroll
    for (int q = 0; q < 4; q++) acc[q] = make_float4(0.f, 0.f, 0.f, 0.f);

    int n = 0;
    for (; n + 8 <= cnt; n += 8) {
        float2 t[8];
        #pragma unroll
        for (int q = 0; q < 8; q++) t[q] = pj[n + q];
        float4 h[8];
        #pragma unroll
        for (int q = 0; q < 8; q++)
            h[q] = Hb[__float_as_int(t[q].y) + lane];
        #pragma unroll
        for (int q = 0; q < 8; q++) {
            acc[q & 3].x = fmaf(t[q].x, h[q].x, acc[q & 3].x);
            acc[q & 3].y = fmaf(t[q].x, h[q].y, acc[q & 3].y);
            acc[q & 3].z = fmaf(t[q].x, h[q].z, acc[q & 3].z);
            acc[q & 3].w = fmaf(t[q].x, h[q].w, acc[q & 3].w);
        }
    }
    for (; n < cnt; n++) {
        const float2 t = pj[n];
        const float4 h0 = Hb[__float_as_int(t.y) + lane];
        acc[0].x = fmaf(t.x, h0.x, acc[0].x);
        acc[0].y = fmaf(t.x, h0.y, acc[0].y);
        acc[0].z = fmaf(t.x, h0.z, acc[0].z);
        acc[0].w = fmaf(t.x, h0.w, acc[0].w);
    }

    float4 r;
    r.x = ((acc[0].x + acc[1].x) + (acc[2].x + acc[3].x)) * inv;
    r.y = ((acc[0].y + acc[1].y) + (acc[2].y + acc[3].y)) * inv;
    r.z = ((acc[0].z + acc[1].z) + (acc[2].z + acc[3].z)) * inv;
    r.w = ((acc[0].w + acc[1].w) + (acc[2].w + acc[3].w)) * inv;
    r.x = (r.x > 0.0f) ? r.x : (expf(r.x) - 1.0f);
    r.y = (r.y > 0.0f) ? r.y : (expf(r.y) - 1.0f);
    r.z = (r.z > 0.0f) ? r.z : (expf(r.z) - 1.0f);
    r.w = (r.w > 0.0f) ? r.w : (expf(r.w) - 1.0f);
    ((float4*)out)[((long)b * Nn + i) * 32 + lane] = r;
}

// ---------------------------------------------------------------------------
extern "C" void kernel_launch(void* const* d_in, const int* in_sizes, int n_in,
                              void* d_out, int out_size) {
    const float* x     = (const float*)d_in[0];   // [8, 2048, 128]
    const float* adj   = (const float*)d_in[1];   // [2048, 2048]
    const float* W     = (const float*)d_in[2];   // [128, 128]
    const float* a_src = (const float*)d_in[3];   // [128, 1]
    const float* a_dst = (const float*)d_in[4];   // [128, 1]
    float* out = (float*)d_out;                   // [8, 2048, 128]
    (void)in_sizes; (void)n_in; (void)out_size;

    fused_front_kernel<<<512, 256>>>(x, adj, W, a_src, a_dst);
    agg_kernel<<<Bn * Nn / 4, 128>>>(out);
}